// round 14
// baseline (speedup 1.0000x reference)
#include <cuda_runtime.h>
#include <cuda_fp16.h>
#include <math.h>
#include <stdint.h>

#define BB 2
#define SS 4096
#define HH 768
#define NHH 12
#define DHH 64
#define MM (BB * SS)
#define NBH (BB * NHH)

typedef unsigned long long u64;
typedef unsigned int u32;

// fp16 scratch
__device__ __half g_xh[(size_t)MM * HH];
__device__ __half g_wq[(size_t)HH * HH];
__device__ __half g_wk[(size_t)HH * HH];
__device__ __half g_wv[(size_t)HH * HH];
__device__ __half g_qh[(size_t)NBH * SS * DHH];   // Q pre-scaled by 0.125*log2(e)
__device__ __half g_kh[(size_t)NBH * SS * DHH];
__device__ __half g_vh[(size_t)NBH * SS * DHH];

__device__ __forceinline__ u32 smem_u32(const void* p) {
    u32 a; asm("{ .reg .u64 t; cvta.to.shared.u64 t, %1; cvt.u32.u64 %0, t; }" : "=r"(a) : "l"(p));
    return a;
}

// ---------------- mma.sync / ldmatrix / cp.async ----------------
#define LDSM4(r, a) \
    asm volatile("ldmatrix.sync.aligned.m8n8.x4.shared.b16 {%0,%1,%2,%3}, [%4];" \
        : "=r"((r)[0]), "=r"((r)[1]), "=r"((r)[2]), "=r"((r)[3]) : "r"(a))
#define LDSM4T(r, a) \
    asm volatile("ldmatrix.sync.aligned.m8n8.x4.trans.shared.b16 {%0,%1,%2,%3}, [%4];" \
        : "=r"((r)[0]), "=r"((r)[1]), "=r"((r)[2]), "=r"((r)[3]) : "r"(a))
// fp32-accumulator MMA
#define MMA(c, a, b0v, b1v) \
    asm volatile("mma.sync.aligned.m16n8k16.row.col.f32.f16.f16.f32 " \
        "{%0,%1,%2,%3}, {%4,%5,%6,%7}, {%8,%9}, {%0,%1,%2,%3};" \
        : "+f"((c)[0]), "+f"((c)[1]), "+f"((c)[2]), "+f"((c)[3]) \
        : "r"((a)[0]), "r"((a)[1]), "r"((a)[2]), "r"((a)[3]), "r"(b0v), "r"(b1v))
// fp16-accumulator MMA (QK path)
#define MMAH(c, a, b0v, b1v) \
    asm volatile("mma.sync.aligned.m16n8k16.row.col.f16.f16.f16.f16 " \
        "{%0,%1}, {%2,%3,%4,%5}, {%6,%7}, {%0,%1};" \
        : "+r"((c)[0]), "+r"((c)[1]) \
        : "r"((a)[0]), "r"((a)[1]), "r"((a)[2]), "r"((a)[3]), "r"(b0v), "r"(b1v))
__device__ __forceinline__ void cp16(u32 saddr, const void* g) {
    asm volatile("cp.async.cg.shared.global [%0], [%1], 16;" :: "r"(saddr), "l"(g));
}
#define CP_COMMIT() asm volatile("cp.async.commit_group;")
#define CP_WAIT0()  asm volatile("cp.async.wait_group 0;")
#define CP_WAIT1()  asm volatile("cp.async.wait_group 1;")
__device__ __forceinline__ u32 cvtpack(float lo, float hi) {
    u32 d; asm("cvt.rn.f16x2.f32 %0, %1, %2;" : "=r"(d) : "f"(hi), "f"(lo)); return d;
}
__device__ __forceinline__ u32 ex2h2(u32 x) {
    u32 r; asm("ex2.approx.f16x2 %0, %1;" : "=r"(r) : "r"(x)); return r;
}
__device__ __forceinline__ u32 haddp(u32 a, u32 b) {
    u32 r; asm("add.rn.f16x2 %0, %1, %2;" : "=r"(r) : "r"(a), "r"(b)); return r;
}

// ---------------------------------------------------------------------------
// fp32 -> fp16 convert: x (8192 rows) + Wq/Wk/Wv (768 rows each) in ONE launch
// ---------------------------------------------------------------------------
__global__ __launch_bounds__(192)
void conv_all_kernel(const float* __restrict__ x_f,
                     const float* __restrict__ wq_f, const float* __restrict__ wk_f,
                     const float* __restrict__ wv_f,
                     __half* __restrict__ x_h,
                     __half* __restrict__ wq_h, __half* __restrict__ wk_h,
                     __half* __restrict__ wv_h)
{
    const int bid = blockIdx.x;
    const float* src;
    __half* dst;
    int row;
    if (bid < MM) { src = x_f; dst = x_h; row = bid; }
    else {
        int r = bid - MM;
        int z = r / HH;
        row = r % HH;
        src = (z == 0) ? wq_f : (z == 1) ? wk_f : wv_f;
        dst = (z == 0) ? wq_h : (z == 1) ? wk_h : wv_h;
    }
    const size_t o = (size_t)row * HH + threadIdx.x * 4;
    float4 v = *(const float4*)&src[o];
    *(uint2*)&dst[o] = make_uint2(cvtpack(v.x, v.y), cvtpack(v.z, v.w));
}

// ---------------------------------------------------------------------------
// fp16 tensor-core GEMM + bias + head-layout fp16 epilogue.
// 3-stage cp.async pipeline, 2 CTAs/SM, single barrier per k-chunk.
// ---------------------------------------------------------------------------
#define XRS 144
#define WRS 272
#define GXT (128 * XRS)
#define GWT (64 * WRS)
#define GBUF (GXT + GWT)           // 35840
#define GSM  (3 * GBUF)            // 107520

__global__ __launch_bounds__(256, 2)
void gemm_tc_kernel(const __half* __restrict__ Xh,
                    const __half* __restrict__ Wq_h, const __half* __restrict__ Wk_h,
                    const __half* __restrict__ Wv_h,
                    const float* __restrict__ bq, const float* __restrict__ bk,
                    const float* __restrict__ bv,
                    __half* __restrict__ qo, __half* __restrict__ ko,
                    __half* __restrict__ vo)
{
    const int z = blockIdx.z;
    const __half* Wh = (z == 0) ? Wq_h : (z == 1) ? Wk_h : Wv_h;
    const float* bias = (z == 0) ? bq : (z == 1) ? bk : bv;
    __half* gout = (z == 0) ? qo : (z == 1) ? ko : vo;
    const float scale = (z == 0) ? 0.18033688011112042f : 1.0f;

    extern __shared__ char smem[];
    const u32 sb = smem_u32(smem);
    const int tid = threadIdx.x;
    const int w = tid >> 5, lane = tid & 31;
    const int wm = w >> 1, wn = w & 1;
    const int bn = blockIdx.x * 128;
    const int bm = blockIdx.y * 128;

    float acc[2][8][4];
    #pragma unroll
    for (int mi = 0; mi < 2; mi++)
        #pragma unroll
        for (int j = 0; j < 8; j++)
            #pragma unroll
            for (int i = 0; i < 4; i++) acc[mi][j][i] = 0.0f;

    const int frow = (lane & 7) + ((lane >> 3) & 1) * 8;
    const u32 aoff = (u32)(frow * XRS + (lane >> 4) * 16);
    const u32 boff = (u32)(frow * WRS + (lane >> 4) * 16);

    // loader indices
    const int xr = tid >> 3, xo = tid & 7;        // X tile: 128 rows x 8 chunks x4 iters
    const int wr = tid >> 4, wo = tid & 15;       // W tile: 64 rows x 16 chunks x4 iters

    // prologue: issue chunks 0 and 1
    #pragma unroll
    for (int pc = 0; pc < 2; pc++) {
        const u32 buf = sb + pc * GBUF;
        const int kb = pc * 64;
        #pragma unroll
        for (int i = 0; i < 4; i++) {
            int r = xr + i * 32;
            cp16(buf + (u32)(r * XRS + xo * 16), Xh + (size_t)(bm + r) * HH + kb + xo * 8);
        }
        #pragma unroll
        for (int i = 0; i < 4; i++) {
            int r = wr + i * 16;
            cp16(buf + GXT + (u32)(r * WRS + wo * 16), Wh + (size_t)(kb + r) * HH + bn + wo * 8);
        }
        CP_COMMIT();
    }

    for (int kc = 0; kc < 12; kc++) {
        if (kc < 11) { CP_WAIT1(); } else { CP_WAIT0(); }
        __syncthreads();

        // issue chunk kc+2 into buffer (kc+2)%3
        if (kc < 10) {
            const u32 buf = sb + ((kc + 2) % 3) * GBUF;
            const int kb = (kc + 2) * 64;
            #pragma unroll
            for (int i = 0; i < 4; i++) {
                int r = xr + i * 32;
                cp16(buf + (u32)(r * XRS + xo * 16), Xh + (size_t)(bm + r) * HH + kb + xo * 8);
            }
            #pragma unroll
            for (int i = 0; i < 4; i++) {
                int r = wr + i * 16;
                cp16(buf + GXT + (u32)(r * WRS + wo * 16), Wh + (size_t)(kb + r) * HH + bn + wo * 8);
            }
            CP_COMMIT();
        }

        const u32 XT = sb + (kc % 3) * GBUF;
        const u32 WT = XT + GXT;

        #pragma unroll
        for (int kk = 0; kk < 4; kk++) {
            u32 ah[2][4];
            #pragma unroll
            for (int mi = 0; mi < 2; mi++) {
                u32 a = (u32)((wm * 32 + mi * 16) * XRS) + aoff + kk * 32;
                LDSM4(ah[mi], XT + a);
            }
            #pragma unroll
            for (int nt = 0; nt < 4; nt++) {
                u32 bo = (u32)(kk * 16 * WRS) + boff + (u32)(wn * 128 + nt * 32);
                u32 bh[4];
                LDSM4T(bh, WT + bo);
                #pragma unroll
                for (int mi = 0; mi < 2; mi++) {
                    MMA(acc[mi][2 * nt],     ah[mi], bh[0], bh[1]);
                    MMA(acc[mi][2 * nt + 1], ah[mi], bh[2], bh[3]);
                }
            }
        }
    }

    const int h  = (bn >> 6) + wn;
    const int cl = (lane & 3) * 2;
    const int rl = lane >> 2;
    #pragma unroll
    for (int j = 0; j < 8; j++) {
        const int d = j * 8 + cl;
        const float bx = bias[bn + wn * 64 + d];
        const float by = bias[bn + wn * 64 + d + 1];
        #pragma unroll
        for (int mi = 0; mi < 2; mi++) {
            #pragma unroll
            for (int rr = 0; rr < 2; rr++) {
                const int m = bm + wm * 32 + mi * 16 + rl + rr * 8;
                const int b = m >> 12, s = m & 4095;
                const size_t o = ((size_t)(b * NHH + h) * SS + s) * DHH + d;
                const float y0 = (acc[mi][j][2 * rr]     + bx) * scale;
                const float y1 = (acc[mi][j][2 * rr + 1] + by) * scale;
                *(u32*)&gout[o] = cvtpack(y0, y1);
            }
        }
    }
}

// ---------------------------------------------------------------------------
// mma.sync flash attention v5 (unchanged from R12/R13 best):
// 4 warps x 32 q-rows, 2 CTAs/SM, software-pipelined (j,mi) stages.
// ---------------------------------------------------------------------------
#define RS 144
#define ARR_BYTES (128 * RS)
#define BUF_BYTES (2 * ARR_BYTES)
#define SM_TOTAL  (2 * BUF_BYTES)     // 73728

__global__ __launch_bounds__(128, 2)
void attn_mma_kernel(const __half* __restrict__ qh_g,
                     const __half* __restrict__ kh_g,
                     const __half* __restrict__ vh_g,
                     float* __restrict__ out)
{
    extern __shared__ char smem[];
    const u32 sb = smem_u32(smem);
    const int tid  = threadIdx.x;
    const int w    = tid >> 5;
    const int lane = tid & 31;
    const int qt = blockIdx.x;
    const int bh = blockIdx.y;
    const int b = bh / NHH, h = bh % NHH;

    const size_t bh_base = (size_t)bh * SS * DHH;

    // ---- stage Q (128 rows) into buffer 1, extract 2 A-fragments/warp ----
    {
        const u32 QB = sb + BUF_BYTES;
        const __half* qg = qh_g + bh_base + (size_t)qt * 128 * DHH;
        #pragma unroll
        for (int i = 0; i < 8; i++) {
            int c = tid + i * 128;
            int r = c >> 3, o = c & 7;
            cp16(QB + (u32)(r * RS + o * 16), qg + (size_t)r * DHH + o * 8);
        }
        CP_COMMIT();
        CP_WAIT0();
        __syncthreads();
    }

    const int frow = (lane & 7) + ((lane >> 3) & 1) * 8;
    u32 qf[2][4][4];
    {
        const u32 QB = sb + BUF_BYTES;
        #pragma unroll
        for (int mi = 0; mi < 2; mi++) {
            u32 rbase = (u32)((w * 32 + mi * 16 + frow) * RS + (lane >> 4) * 16);
            #pragma unroll
            for (int k = 0; k < 4; k++)
                LDSM4(qf[mi][k], QB + rbase + k * 32);
        }
    }
    __syncthreads();

    float ctx[2][8][4];
    #pragma unroll
    for (int mi = 0; mi < 2; mi++)
        #pragma unroll
        for (int n = 0; n < 8; n++)
            #pragma unroll
            for (int i = 0; i < 4; i++) ctx[mi][n][i] = 0.0f;
    float ls[2][2] = {{0.f, 0.f}, {0.f, 0.f}};

    const u32 koff = (u32)(((lane >> 4) * 8 + (lane & 7)) * RS + ((lane >> 3) & 1) * 16);
    const u32 voff = (u32)((((lane >> 3) & 1) * 8 + (lane & 7)) * RS + (lane >> 4) * 16);

    // tile 0 -> buffer 0
    {
        #pragma unroll
        for (int i = 0; i < 8; i++) {
            int c = tid + i * 128;
            int r = c >> 3, o = c & 7;
            u32 so = (u32)(r * RS + o * 16);
            cp16(sb + so,             kh_g + bh_base + (size_t)r * DHH + o * 8);
            cp16(sb + ARR_BYTES + so, vh_g + bh_base + (size_t)r * DHH + o * 8);
        }
        CP_COMMIT();
    }

    for (int t = 0; t < 32; ++t) {
        if (t < 31) {
            const u32 nb = sb + ((t + 1) & 1) * BUF_BYTES;
            const size_t gb = bh_base + (size_t)(t + 1) * 128 * DHH;
            #pragma unroll
            for (int i = 0; i < 8; i++) {
                int c = tid + i * 128;
                int r = c >> 3, o = c & 7;
                u32 so = (u32)(r * RS + o * 16);
                cp16(nb + so,             kh_g + gb + (size_t)r * DHH + o * 8);
                cp16(nb + ARR_BYTES + so, vh_g + gb + (size_t)r * DHH + o * 8);
            }
            CP_COMMIT();
            CP_WAIT1();
        } else {
            CP_WAIT0();
        }
        __syncthreads();

        const u32 KH = sb + (t & 1) * BUF_BYTES;
        const u32 VS = KH + ARR_BYTES;

        u32 hls[2][2] = {{0u, 0u}, {0u, 0u}};

        u32 khf[4][4];
        #pragma unroll
        for (int k = 0; k < 4; k++)
            LDSM4(khf[k], KH + koff + k * 32);

        u32 scur[4] = {0u, 0u, 0u, 0u};
        #pragma unroll
        for (int k = 0; k < 4; k++) {
            MMAH(&scur[0], qf[0][k], khf[k][0], khf[k][1]);
            MMAH(&scur[2], qf[0][k], khf[k][2], khf[k][3]);
        }

        u32 vf[4][4];

        #pragma unroll
        for (int st = 0; st < 16; st++) {
            const int j  = st >> 1;
            const int mi = st & 1;

            if (mi == 0) {
                const u32 bj = (u32)(j * 16 * RS);
                #pragma unroll
                for (int tt = 0; tt < 4; tt++)
                    LDSM4T(vf[tt], VS + bj + voff + tt * 32);
            }

            u32 pa[4];
            pa[0] = ex2h2(scur[0]);
            pa[1] = ex2h2(scur[1]);
            pa[2] = ex2h2(scur[2]);
            pa[3] = ex2h2(scur[3]);

            u32 snext[4] = {0u, 0u, 0u, 0u};
            if (st < 15) {
                const int mi2 = (st + 1) & 1;
                if (mi2 == 0) {
                    const int j2 = (st + 1) >> 1;
                    const u32 bj2 = (u32)(j2 * 16 * RS);
                    #pragma unroll
                    for (int k = 0; k < 4; k++)
                        LDSM4(khf[k], KH + bj2 + koff + k * 32);
                }
                #pragma unroll
                for (int k = 0; k < 4; k++) {
                    MMAH(&snext[0], qf[mi2][k], khf[k][0], khf[k][1]);
                    MMAH(&snext[2], qf[mi2][k], khf[k][2], khf[k][3]);
                }
            }

            hls[mi][0] = haddp(hls[mi][0], haddp(pa[0], pa[2]));
            hls[mi][1] = haddp(hls[mi][1], haddp(pa[1], pa[3]));

            #pragma unroll
            for (int tt = 0; tt < 4; tt++) {
                MMA(ctx[mi][2 * tt],     pa, vf[tt][0], vf[tt][1]);
                MMA(ctx[mi][2 * tt + 1], pa, vf[tt][2], vf[tt][3]);
            }

            #pragma unroll
            for (int i = 0; i < 4; i++) scur[i] = snext[i];
        }

        #pragma unroll
        for (int mi = 0; mi < 2; mi++) {
            float2 f0 = __half22float2(*(__half2*)&hls[mi][0]);
            float2 f1 = __half22float2(*(__half2*)&hls[mi][1]);
            ls[mi][0] += f0.x + f0.y;
            ls[mi][1] += f1.x + f1.y;
        }
        __syncthreads();
    }

    #pragma unroll
    for (int mi = 0; mi < 2; mi++) {
        float l0 = ls[mi][0], l1 = ls[mi][1];
        l0 += __shfl_xor_sync(0xffffffffu, l0, 1);
        l0 += __shfl_xor_sync(0xffffffffu, l0, 2);
        l1 += __shfl_xor_sync(0xffffffffu, l1, 1);
        l1 += __shfl_xor_sync(0xffffffffu, l1, 2);
        const float inv0 = 1.0f / l0;
        const float inv1 = 1.0f / l1;

        const int row0 = qt * 128 + w * 32 + mi * 16 + (lane >> 2);
        const int colb = 2 * (lane & 3);
        float* o0 = out + ((size_t)(b * SS) + row0) * HH + h * DHH + colb;
        float* o1 = o0 + 8 * HH;
        #pragma unroll
        for (int n = 0; n < 8; n++) {
            float2 r0, r1;
            r0.x = tanhf(ctx[mi][n][0] * inv0);
            r0.y = tanhf(ctx[mi][n][1] * inv0);
            r1.x = tanhf(ctx[mi][n][2] * inv1);
            r1.y = tanhf(ctx[mi][n][3] * inv1);
            *(float2*)(o0 + 8 * n) = r0;
            *(float2*)(o1 + 8 * n) = r1;
        }
    }
}

// ---------------------------------------------------------------------------
extern "C" void kernel_launch(void* const* d_in, const int* in_sizes, int n_in,
                              void* d_out, int out_size)
{
    const float* x  = (const float*)d_in[0];
    const float* Wq = (const float*)d_in[1];
    const float* bq = (const float*)d_in[2];
    const float* Wk = (const float*)d_in[3];
    const float* bk = (const float*)d_in[4];
    const float* Wv = (const float*)d_in[5];
    const float* bv = (const float*)d_in[6];
    float* out = (float*)d_out;

    __half *xh, *wq, *wk, *wv, *qh, *kh, *vh;
    cudaGetSymbolAddress((void**)&xh, g_xh);
    cudaGetSymbolAddress((void**)&wq, g_wq);
    cudaGetSymbolAddress((void**)&wk, g_wk);
    cudaGetSymbolAddress((void**)&wv, g_wv);
    cudaGetSymbolAddress((void**)&qh, g_qh);
    cudaGetSymbolAddress((void**)&kh, g_kh);
    cudaGetSymbolAddress((void**)&vh, g_vh);

    cudaFuncSetAttribute(gemm_tc_kernel, cudaFuncAttributeMaxDynamicSharedMemorySize, GSM);
    cudaFuncSetAttribute(attn_mma_kernel, cudaFuncAttributeMaxDynamicSharedMemorySize, SM_TOTAL);

    conv_all_kernel<<<MM + 3 * HH, 192>>>(x, Wq, Wk, Wv, xh, wq, wk, wv);

    dim3 ggrid(HH / 128, MM / 128, 3);
    gemm_tc_kernel<<<ggrid, 256, GSM>>>(xh, wq, wk, wv, bq, bk, bv, qh, kh, vh);

    dim3 agrid(SS / 128, NBH);
    attn_mma_kernel<<<agrid, 128, SM_TOTAL>>>(qh, kh, vh, out);
}

// round 15
// speedup vs baseline: 1.0259x; 1.0259x over previous
#include <cuda_runtime.h>
#include <cuda_fp16.h>
#include <math.h>
#include <stdint.h>

#define BB 2
#define SS 4096
#define HH 768
#define NHH 12
#define DHH 64
#define MM (BB * SS)
#define NBH (BB * NHH)
#define KVSPLIT 2

typedef unsigned long long u64;
typedef unsigned int u32;

// fp16 scratch
__device__ __half g_xh[(size_t)MM * HH];
__device__ __half g_wq[(size_t)HH * HH];
__device__ __half g_wk[(size_t)HH * HH];
__device__ __half g_wv[(size_t)HH * HH];
__device__ __half g_qh[(size_t)NBH * SS * DHH];   // Q pre-scaled by 0.125*log2(e)
__device__ __half g_kh[(size_t)NBH * SS * DHH];
__device__ __half g_vh[(size_t)NBH * SS * DHH];
// kv-split partials
__device__ float g_pctx[KVSPLIT][(size_t)MM * HH];   // unnormalized ctx, out layout
__device__ float g_pl[KVSPLIT][(size_t)NBH * SS];    // row sums

__device__ __forceinline__ u32 smem_u32(const void* p) {
    u32 a; asm("{ .reg .u64 t; cvta.to.shared.u64 t, %1; cvt.u32.u64 %0, t; }" : "=r"(a) : "l"(p));
    return a;
}

// ---------------- mma.sync / ldmatrix / cp.async ----------------
#define LDSM4(r, a) \
    asm volatile("ldmatrix.sync.aligned.m8n8.x4.shared.b16 {%0,%1,%2,%3}, [%4];" \
        : "=r"((r)[0]), "=r"((r)[1]), "=r"((r)[2]), "=r"((r)[3]) : "r"(a))
#define LDSM4T(r, a) \
    asm volatile("ldmatrix.sync.aligned.m8n8.x4.trans.shared.b16 {%0,%1,%2,%3}, [%4];" \
        : "=r"((r)[0]), "=r"((r)[1]), "=r"((r)[2]), "=r"((r)[3]) : "r"(a))
#define MMA(c, a, b0v, b1v) \
    asm volatile("mma.sync.aligned.m16n8k16.row.col.f32.f16.f16.f32 " \
        "{%0,%1,%2,%3}, {%4,%5,%6,%7}, {%8,%9}, {%0,%1,%2,%3};" \
        : "+f"((c)[0]), "+f"((c)[1]), "+f"((c)[2]), "+f"((c)[3]) \
        : "r"((a)[0]), "r"((a)[1]), "r"((a)[2]), "r"((a)[3]), "r"(b0v), "r"(b1v))
#define MMAH(c, a, b0v, b1v) \
    asm volatile("mma.sync.aligned.m16n8k16.row.col.f16.f16.f16.f16 " \
        "{%0,%1}, {%2,%3,%4,%5}, {%6,%7}, {%0,%1};" \
        : "+r"((c)[0]), "+r"((c)[1]) \
        : "r"((a)[0]), "r"((a)[1]), "r"((a)[2]), "r"((a)[3]), "r"(b0v), "r"(b1v))
__device__ __forceinline__ void cp16(u32 saddr, const void* g) {
    asm volatile("cp.async.cg.shared.global [%0], [%1], 16;" :: "r"(saddr), "l"(g));
}
#define CP_COMMIT() asm volatile("cp.async.commit_group;")
#define CP_WAIT0()  asm volatile("cp.async.wait_group 0;")
#define CP_WAIT1()  asm volatile("cp.async.wait_group 1;")
__device__ __forceinline__ u32 cvtpack(float lo, float hi) {
    u32 d; asm("cvt.rn.f16x2.f32 %0, %1, %2;" : "=r"(d) : "f"(hi), "f"(lo)); return d;
}
__device__ __forceinline__ u32 ex2h2(u32 x) {
    u32 r; asm("ex2.approx.f16x2 %0, %1;" : "=r"(r) : "r"(x)); return r;
}
__device__ __forceinline__ u32 haddp(u32 a, u32 b) {
    u32 r; asm("add.rn.f16x2 %0, %1, %2;" : "=r"(r) : "r"(a), "r"(b)); return r;
}

// ---------------------------------------------------------------------------
// fp32 -> fp16 convert: x + Wq/Wk/Wv in ONE launch
// ---------------------------------------------------------------------------
__global__ __launch_bounds__(192)
void conv_all_kernel(const float* __restrict__ x_f,
                     const float* __restrict__ wq_f, const float* __restrict__ wk_f,
                     const float* __restrict__ wv_f,
                     __half* __restrict__ x_h,
                     __half* __restrict__ wq_h, __half* __restrict__ wk_h,
                     __half* __restrict__ wv_h)
{
    const int bid = blockIdx.x;
    const float* src;
    __half* dst;
    int row;
    if (bid < MM) { src = x_f; dst = x_h; row = bid; }
    else {
        int r = bid - MM;
        int z = r / HH;
        row = r % HH;
        src = (z == 0) ? wq_f : (z == 1) ? wk_f : wv_f;
        dst = (z == 0) ? wq_h : (z == 1) ? wk_h : wv_h;
    }
    const size_t o = (size_t)row * HH + threadIdx.x * 4;
    float4 v = *(const float4*)&src[o];
    *(uint2*)&dst[o] = make_uint2(cvtpack(v.x, v.y), cvtpack(v.z, v.w));
}

// ---------------------------------------------------------------------------
// fp16 tensor-core GEMM + bias + head-layout fp16 epilogue.
// 3-stage cp.async pipeline, 2 CTAs/SM.
// ---------------------------------------------------------------------------
#define XRS 144
#define WRS 272
#define GXT (128 * XRS)
#define GWT (64 * WRS)
#define GBUF (GXT + GWT)
#define GSM  (3 * GBUF)

__global__ __launch_bounds__(256, 2)
void gemm_tc_kernel(const __half* __restrict__ Xh,
                    const __half* __restrict__ Wq_h, const __half* __restrict__ Wk_h,
                    const __half* __restrict__ Wv_h,
                    const float* __restrict__ bq, const float* __restrict__ bk,
                    const float* __restrict__ bv,
                    __half* __restrict__ qo, __half* __restrict__ ko,
                    __half* __restrict__ vo)
{
    const int z = blockIdx.z;
    const __half* Wh = (z == 0) ? Wq_h : (z == 1) ? Wk_h : Wv_h;
    const float* bias = (z == 0) ? bq : (z == 1) ? bk : bv;
    __half* gout = (z == 0) ? qo : (z == 1) ? ko : vo;
    const float scale = (z == 0) ? 0.18033688011112042f : 1.0f;

    extern __shared__ char smem[];
    const u32 sb = smem_u32(smem);
    const int tid = threadIdx.x;
    const int w = tid >> 5, lane = tid & 31;
    const int wm = w >> 1, wn = w & 1;
    const int bn = blockIdx.x * 128;
    const int bm = blockIdx.y * 128;

    float acc[2][8][4];
    #pragma unroll
    for (int mi = 0; mi < 2; mi++)
        #pragma unroll
        for (int j = 0; j < 8; j++)
            #pragma unroll
            for (int i = 0; i < 4; i++) acc[mi][j][i] = 0.0f;

    const int frow = (lane & 7) + ((lane >> 3) & 1) * 8;
    const u32 aoff = (u32)(frow * XRS + (lane >> 4) * 16);
    const u32 boff = (u32)(frow * WRS + (lane >> 4) * 16);

    const int xr = tid >> 3, xo = tid & 7;
    const int wr = tid >> 4, wo = tid & 15;

    #pragma unroll
    for (int pc = 0; pc < 2; pc++) {
        const u32 buf = sb + pc * GBUF;
        const int kb = pc * 64;
        #pragma unroll
        for (int i = 0; i < 4; i++) {
            int r = xr + i * 32;
            cp16(buf + (u32)(r * XRS + xo * 16), Xh + (size_t)(bm + r) * HH + kb + xo * 8);
        }
        #pragma unroll
        for (int i = 0; i < 4; i++) {
            int r = wr + i * 16;
            cp16(buf + GXT + (u32)(r * WRS + wo * 16), Wh + (size_t)(kb + r) * HH + bn + wo * 8);
        }
        CP_COMMIT();
    }

    for (int kc = 0; kc < 12; kc++) {
        if (kc < 11) { CP_WAIT1(); } else { CP_WAIT0(); }
        __syncthreads();

        if (kc < 10) {
            const u32 buf = sb + ((kc + 2) % 3) * GBUF;
            const int kb = (kc + 2) * 64;
            #pragma unroll
            for (int i = 0; i < 4; i++) {
                int r = xr + i * 32;
                cp16(buf + (u32)(r * XRS + xo * 16), Xh + (size_t)(bm + r) * HH + kb + xo * 8);
            }
            #pragma unroll
            for (int i = 0; i < 4; i++) {
                int r = wr + i * 16;
                cp16(buf + GXT + (u32)(r * WRS + wo * 16), Wh + (size_t)(kb + r) * HH + bn + wo * 8);
            }
            CP_COMMIT();
        }

        const u32 XT = sb + (kc % 3) * GBUF;
        const u32 WT = XT + GXT;

        #pragma unroll
        for (int kk = 0; kk < 4; kk++) {
            u32 ah[2][4];
            #pragma unroll
            for (int mi = 0; mi < 2; mi++) {
                u32 a = (u32)((wm * 32 + mi * 16) * XRS) + aoff + kk * 32;
                LDSM4(ah[mi], XT + a);
            }
            #pragma unroll
            for (int nt = 0; nt < 4; nt++) {
                u32 bo = (u32)(kk * 16 * WRS) + boff + (u32)(wn * 128 + nt * 32);
                u32 bh[4];
                LDSM4T(bh, WT + bo);
                #pragma unroll
                for (int mi = 0; mi < 2; mi++) {
                    MMA(acc[mi][2 * nt],     ah[mi], bh[0], bh[1]);
                    MMA(acc[mi][2 * nt + 1], ah[mi], bh[2], bh[3]);
                }
            }
        }
    }

    const int h  = (bn >> 6) + wn;
    const int cl = (lane & 3) * 2;
    const int rl = lane >> 2;
    #pragma unroll
    for (int j = 0; j < 8; j++) {
        const int d = j * 8 + cl;
        const float bx = bias[bn + wn * 64 + d];
        const float by = bias[bn + wn * 64 + d + 1];
        #pragma unroll
        for (int mi = 0; mi < 2; mi++) {
            #pragma unroll
            for (int rr = 0; rr < 2; rr++) {
                const int m = bm + wm * 32 + mi * 16 + rl + rr * 8;
                const int b = m >> 12, s = m & 4095;
                const size_t o = ((size_t)(b * NHH + h) * SS + s) * DHH + d;
                const float y0 = (acc[mi][j][2 * rr]     + bx) * scale;
                const float y1 = (acc[mi][j][2 * rr + 1] + by) * scale;
                *(u32*)&gout[o] = cvtpack(y0, y1);
            }
        }
    }
}

// ---------------------------------------------------------------------------
// mma.sync flash attention v6: v5 pipeline, KV-split 2x (blockIdx.z = half).
// Writes unnormalized partial ctx + row sums to scratch.
// ---------------------------------------------------------------------------
#define RS 144
#define ARR_BYTES (128 * RS)
#define BUF_BYTES (2 * ARR_BYTES)
#define SM_TOTAL  (2 * BUF_BYTES)
#define NT_HALF (32 / KVSPLIT)        // 16 key tiles per CTA

__global__ __launch_bounds__(128, 2)
void attn_mma_kernel(const __half* __restrict__ qh_g,
                     const __half* __restrict__ kh_g,
                     const __half* __restrict__ vh_g,
                     float* __restrict__ pctx0, float* __restrict__ pctx1,
                     float* __restrict__ pl0, float* __restrict__ pl1)
{
    extern __shared__ char smem[];
    const u32 sb = smem_u32(smem);
    const int tid  = threadIdx.x;
    const int w    = tid >> 5;
    const int lane = tid & 31;
    const int qt = blockIdx.x;
    const int bh = blockIdx.y;
    const int kz = blockIdx.z;            // kv half
    const int b = bh / NHH, h = bh % NHH;
    float* __restrict__ pctx = kz ? pctx1 : pctx0;
    float* __restrict__ pl   = kz ? pl1 : pl0;

    const size_t bh_base = (size_t)bh * SS * DHH;
    const int t0 = kz * NT_HALF;

    // ---- stage Q (128 rows) into buffer 1, extract 2 A-fragments/warp ----
    {
        const u32 QB = sb + BUF_BYTES;
        const __half* qg = qh_g + bh_base + (size_t)qt * 128 * DHH;
        #pragma unroll
        for (int i = 0; i < 8; i++) {
            int c = tid + i * 128;
            int r = c >> 3, o = c & 7;
            cp16(QB + (u32)(r * RS + o * 16), qg + (size_t)r * DHH + o * 8);
        }
        CP_COMMIT();
        CP_WAIT0();
        __syncthreads();
    }

    const int frow = (lane & 7) + ((lane >> 3) & 1) * 8;
    u32 qf[2][4][4];
    {
        const u32 QB = sb + BUF_BYTES;
        #pragma unroll
        for (int mi = 0; mi < 2; mi++) {
            u32 rbase = (u32)((w * 32 + mi * 16 + frow) * RS + (lane >> 4) * 16);
            #pragma unroll
            for (int k = 0; k < 4; k++)
                LDSM4(qf[mi][k], QB + rbase + k * 32);
        }
    }
    __syncthreads();

    float ctx[2][8][4];
    #pragma unroll
    for (int mi = 0; mi < 2; mi++)
        #pragma unroll
        for (int n = 0; n < 8; n++)
            #pragma unroll
            for (int i = 0; i < 4; i++) ctx[mi][n][i] = 0.0f;
    float ls[2][2] = {{0.f, 0.f}, {0.f, 0.f}};

    const u32 koff = (u32)(((lane >> 4) * 8 + (lane & 7)) * RS + ((lane >> 3) & 1) * 16);
    const u32 voff = (u32)((((lane >> 3) & 1) * 8 + (lane & 7)) * RS + (lane >> 4) * 16);

    // tile t0 -> buffer 0
    {
        const size_t gb = bh_base + (size_t)t0 * 128 * DHH;
        #pragma unroll
        for (int i = 0; i < 8; i++) {
            int c = tid + i * 128;
            int r = c >> 3, o = c & 7;
            u32 so = (u32)(r * RS + o * 16);
            cp16(sb + so,             kh_g + gb + (size_t)r * DHH + o * 8);
            cp16(sb + ARR_BYTES + so, vh_g + gb + (size_t)r * DHH + o * 8);
        }
        CP_COMMIT();
    }

    for (int t = 0; t < NT_HALF; ++t) {
        if (t < NT_HALF - 1) {
            const u32 nb = sb + ((t + 1) & 1) * BUF_BYTES;
            const size_t gb = bh_base + (size_t)(t0 + t + 1) * 128 * DHH;
            #pragma unroll
            for (int i = 0; i < 8; i++) {
                int c = tid + i * 128;
                int r = c >> 3, o = c & 7;
                u32 so = (u32)(r * RS + o * 16);
                cp16(nb + so,             kh_g + gb + (size_t)r * DHH + o * 8);
                cp16(nb + ARR_BYTES + so, vh_g + gb + (size_t)r * DHH + o * 8);
            }
            CP_COMMIT();
            CP_WAIT1();
        } else {
            CP_WAIT0();
        }
        __syncthreads();

        const u32 KH = sb + (t & 1) * BUF_BYTES;
        const u32 VS = KH + ARR_BYTES;

        u32 hls[2][2] = {{0u, 0u}, {0u, 0u}};

        u32 khf[4][4];
        #pragma unroll
        for (int k = 0; k < 4; k++)
            LDSM4(khf[k], KH + koff + k * 32);

        u32 scur[4] = {0u, 0u, 0u, 0u};
        #pragma unroll
        for (int k = 0; k < 4; k++) {
            MMAH(&scur[0], qf[0][k], khf[k][0], khf[k][1]);
            MMAH(&scur[2], qf[0][k], khf[k][2], khf[k][3]);
        }

        u32 vf[4][4];

        #pragma unroll
        for (int st = 0; st < 16; st++) {
            const int j  = st >> 1;
            const int mi = st & 1;

            if (mi == 0) {
                const u32 bj = (u32)(j * 16 * RS);
                #pragma unroll
                for (int tt = 0; tt < 4; tt++)
                    LDSM4T(vf[tt], VS + bj + voff + tt * 32);
            }

            u32 pa[4];
            pa[0] = ex2h2(scur[0]);
            pa[1] = ex2h2(scur[1]);
            pa[2] = ex2h2(scur[2]);
            pa[3] = ex2h2(scur[3]);

            u32 snext[4] = {0u, 0u, 0u, 0u};
            if (st < 15) {
                const int mi2 = (st + 1) & 1;
                if (mi2 == 0) {
                    const int j2 = (st + 1) >> 1;
                    const u32 bj2 = (u32)(j2 * 16 * RS);
                    #pragma unroll
                    for (int k = 0; k < 4; k++)
                        LDSM4(khf[k], KH + bj2 + koff + k * 32);
                }
                #pragma unroll
                for (int k = 0; k < 4; k++) {
                    MMAH(&snext[0], qf[mi2][k], khf[k][0], khf[k][1]);
                    MMAH(&snext[2], qf[mi2][k], khf[k][2], khf[k][3]);
                }
            }

            hls[mi][0] = haddp(hls[mi][0], haddp(pa[0], pa[2]));
            hls[mi][1] = haddp(hls[mi][1], haddp(pa[1], pa[3]));

            #pragma unroll
            for (int tt = 0; tt < 4; tt++) {
                MMA(ctx[mi][2 * tt],     pa, vf[tt][0], vf[tt][1]);
                MMA(ctx[mi][2 * tt + 1], pa, vf[tt][2], vf[tt][3]);
            }

            #pragma unroll
            for (int i = 0; i < 4; i++) scur[i] = snext[i];
        }

        #pragma unroll
        for (int mi = 0; mi < 2; mi++) {
            float2 f0 = __half22float2(*(__half2*)&hls[mi][0]);
            float2 f1 = __half22float2(*(__half2*)&hls[mi][1]);
            ls[mi][0] += f0.x + f0.y;
            ls[mi][1] += f1.x + f1.y;
        }
        __syncthreads();
    }

    // ---- write partial ctx (unnormalized) + partial row sums ----
    #pragma unroll
    for (int mi = 0; mi < 2; mi++) {
        float l0 = ls[mi][0], l1 = ls[mi][1];
        l0 += __shfl_xor_sync(0xffffffffu, l0, 1);
        l0 += __shfl_xor_sync(0xffffffffu, l0, 2);
        l1 += __shfl_xor_sync(0xffffffffu, l1, 1);
        l1 += __shfl_xor_sync(0xffffffffu, l1, 2);

        const int rloc = qt * 128 + w * 32 + mi * 16 + (lane >> 2);
        if ((lane & 3) == 0) {
            pl[(size_t)bh * SS + rloc]     = l0;
            pl[(size_t)bh * SS + rloc + 8] = l1;
        }

        const int colb = 2 * (lane & 3);
        float* o0 = pctx + ((size_t)(b * SS) + rloc) * HH + h * DHH + colb;
        float* o1 = o0 + 8 * HH;
        #pragma unroll
        for (int n = 0; n < 8; n++) {
            *(float2*)(o0 + 8 * n) = make_float2(ctx[mi][n][0], ctx[mi][n][1]);
            *(float2*)(o1 + 8 * n) = make_float2(ctx[mi][n][2], ctx[mi][n][3]);
        }
    }
}

// ---------------------------------------------------------------------------
// Combine: out = tanh((c0+c1)/(l0+l1))
// ---------------------------------------------------------------------------
__global__ __launch_bounds__(256)
void combine_kernel(const float* __restrict__ pctx0, const float* __restrict__ pctx1,
                    const float* __restrict__ pl0, const float* __restrict__ pl1,
                    float* __restrict__ out)
{
    const size_t i4 = (size_t)blockIdx.x * 256 + threadIdx.x;   // float4 index
    const size_t o = i4 * 4;
    const int row = (int)(o / HH);
    const int col = (int)(o % HH);
    const int h = col >> 6;
    const int b = row >> 12, s = row & 4095;
    const size_t li = (size_t)(b * NHH + h) * SS + s;

    const float inv = 1.0f / (pl0[li] + pl1[li]);
    float4 c0 = *(const float4*)&pctx0[o];
    float4 c1 = *(const float4*)&pctx1[o];
    float4 r;
    r.x = tanhf((c0.x + c1.x) * inv);
    r.y = tanhf((c0.y + c1.y) * inv);
    r.z = tanhf((c0.z + c1.z) * inv);
    r.w = tanhf((c0.w + c1.w) * inv);
    *(float4*)&out[o] = r;
}

// ---------------------------------------------------------------------------
extern "C" void kernel_launch(void* const* d_in, const int* in_sizes, int n_in,
                              void* d_out, int out_size)
{
    const float* x  = (const float*)d_in[0];
    const float* Wq = (const float*)d_in[1];
    const float* bq = (const float*)d_in[2];
    const float* Wk = (const float*)d_in[3];
    const float* bk = (const float*)d_in[4];
    const float* Wv = (const float*)d_in[5];
    const float* bv = (const float*)d_in[6];
    float* out = (float*)d_out;

    __half *xh, *wq, *wk, *wv, *qh, *kh, *vh;
    float *pc, *plv;
    cudaGetSymbolAddress((void**)&xh, g_xh);
    cudaGetSymbolAddress((void**)&wq, g_wq);
    cudaGetSymbolAddress((void**)&wk, g_wk);
    cudaGetSymbolAddress((void**)&wv, g_wv);
    cudaGetSymbolAddress((void**)&qh, g_qh);
    cudaGetSymbolAddress((void**)&kh, g_kh);
    cudaGetSymbolAddress((void**)&vh, g_vh);
    cudaGetSymbolAddress((void**)&pc, g_pctx);
    cudaGetSymbolAddress((void**)&plv, g_pl);
    float* pc0 = pc;
    float* pc1 = pc + (size_t)MM * HH;
    float* pl0 = plv;
    float* pl1 = plv + (size_t)NBH * SS;

    cudaFuncSetAttribute(gemm_tc_kernel, cudaFuncAttributeMaxDynamicSharedMemorySize, GSM);
    cudaFuncSetAttribute(attn_mma_kernel, cudaFuncAttributeMaxDynamicSharedMemorySize, SM_TOTAL);

    conv_all_kernel<<<MM + 3 * HH, 192>>>(x, Wq, Wk, Wv, xh, wq, wk, wv);

    dim3 ggrid(HH / 128, MM / 128, 3);
    gemm_tc_kernel<<<ggrid, 256, GSM>>>(xh, wq, wk, wv, bq, bk, bv, qh, kh, vh);

    dim3 agrid(SS / 128, NBH, KVSPLIT);
    attn_mma_kernel<<<agrid, 128, SM_TOTAL>>>(qh, kh, vh, pc0, pc1, pl0, pl1);

    combine_kernel<<<(MM * HH) / (4 * 256), 256>>>(pc0, pc1, pl0, pl1, out);
}

// round 16
// speedup vs baseline: 1.0312x; 1.0052x over previous
#include <cuda_runtime.h>
#include <cuda_fp16.h>
#include <math.h>
#include <stdint.h>

#define BB 2
#define SS 4096
#define HH 768
#define NHH 12
#define DHH 64
#define MM (BB * SS)
#define NBH (BB * NHH)
#define KVSPLIT 2

typedef unsigned long long u64;
typedef unsigned int u32;

// fp16 scratch
__device__ __half g_xh[(size_t)MM * HH];
__device__ __half g_wq[(size_t)HH * HH];
__device__ __half g_wk[(size_t)HH * HH];
__device__ __half g_wv[(size_t)HH * HH];
__device__ __half g_qh[(size_t)NBH * SS * DHH];   // Q pre-scaled by 0.125*log2(e)
__device__ __half g_kh[(size_t)NBH * SS * DHH];
__device__ __half g_vh[(size_t)NBH * SS * DHH];
// kv-split partials (fp16 ctx, fp32 row sums)
__device__ __half g_pctx[KVSPLIT][(size_t)MM * HH];
__device__ float  g_pl[KVSPLIT][(size_t)NBH * SS];

__device__ __forceinline__ u32 smem_u32(const void* p) {
    u32 a; asm("{ .reg .u64 t; cvta.to.shared.u64 t, %1; cvt.u32.u64 %0, t; }" : "=r"(a) : "l"(p));
    return a;
}

// ---------------- mma.sync / ldmatrix / cp.async ----------------
#define LDSM4(r, a) \
    asm volatile("ldmatrix.sync.aligned.m8n8.x4.shared.b16 {%0,%1,%2,%3}, [%4];" \
        : "=r"((r)[0]), "=r"((r)[1]), "=r"((r)[2]), "=r"((r)[3]) : "r"(a))
#define LDSM4T(r, a) \
    asm volatile("ldmatrix.sync.aligned.m8n8.x4.trans.shared.b16 {%0,%1,%2,%3}, [%4];" \
        : "=r"((r)[0]), "=r"((r)[1]), "=r"((r)[2]), "=r"((r)[3]) : "r"(a))
#define MMA(c, a, b0v, b1v) \
    asm volatile("mma.sync.aligned.m16n8k16.row.col.f32.f16.f16.f32 " \
        "{%0,%1,%2,%3}, {%4,%5,%6,%7}, {%8,%9}, {%0,%1,%2,%3};" \
        : "+f"((c)[0]), "+f"((c)[1]), "+f"((c)[2]), "+f"((c)[3]) \
        : "r"((a)[0]), "r"((a)[1]), "r"((a)[2]), "r"((a)[3]), "r"(b0v), "r"(b1v))
#define MMAH(c, a, b0v, b1v) \
    asm volatile("mma.sync.aligned.m16n8k16.row.col.f16.f16.f16.f16 " \
        "{%0,%1}, {%2,%3,%4,%5}, {%6,%7}, {%0,%1};" \
        : "+r"((c)[0]), "+r"((c)[1]) \
        : "r"((a)[0]), "r"((a)[1]), "r"((a)[2]), "r"((a)[3]), "r"(b0v), "r"(b1v))
__device__ __forceinline__ void cp16(u32 saddr, const void* g) {
    asm volatile("cp.async.cg.shared.global [%0], [%1], 16;" :: "r"(saddr), "l"(g));
}
#define CP_COMMIT() asm volatile("cp.async.commit_group;")
#define CP_WAIT0()  asm volatile("cp.async.wait_group 0;")
#define CP_WAIT1()  asm volatile("cp.async.wait_group 1;")
__device__ __forceinline__ u32 cvtpack(float lo, float hi) {
    u32 d; asm("cvt.rn.f16x2.f32 %0, %1, %2;" : "=r"(d) : "f"(hi), "f"(lo)); return d;
}
__device__ __forceinline__ u32 ex2h2(u32 x) {
    u32 r; asm("ex2.approx.f16x2 %0, %1;" : "=r"(r) : "r"(x)); return r;
}
__device__ __forceinline__ u32 haddp(u32 a, u32 b) {
    u32 r; asm("add.rn.f16x2 %0, %1, %2;" : "=r"(r) : "r"(a), "r"(b)); return r;
}

// ---------------------------------------------------------------------------
// fp32 -> fp16 convert: x + Wq/Wk/Wv in ONE launch
// ---------------------------------------------------------------------------
__global__ __launch_bounds__(192)
void conv_all_kernel(const float* __restrict__ x_f,
                     const float* __restrict__ wq_f, const float* __restrict__ wk_f,
                     const float* __restrict__ wv_f,
                     __half* __restrict__ x_h,
                     __half* __restrict__ wq_h, __half* __restrict__ wk_h,
                     __half* __restrict__ wv_h)
{
    const int bid = blockIdx.x;
    const float* src;
    __half* dst;
    int row;
    if (bid < MM) { src = x_f; dst = x_h; row = bid; }
    else {
        int r = bid - MM;
        int z = r / HH;
        row = r % HH;
        src = (z == 0) ? wq_f : (z == 1) ? wk_f : wv_f;
        dst = (z == 0) ? wq_h : (z == 1) ? wk_h : wv_h;
    }
    const size_t o = (size_t)row * HH + threadIdx.x * 4;
    float4 v = *(const float4*)&src[o];
    *(uint2*)&dst[o] = make_uint2(cvtpack(v.x, v.y), cvtpack(v.z, v.w));
}

// ---------------------------------------------------------------------------
// fp16 tensor-core GEMM + bias + head-layout fp16 epilogue.
// 3-stage cp.async pipeline, 2 CTAs/SM.
// ---------------------------------------------------------------------------
#define XRS 144
#define WRS 272
#define GXT (128 * XRS)
#define GWT (64 * WRS)
#define GBUF (GXT + GWT)
#define GSM  (3 * GBUF)

__global__ __launch_bounds__(256, 2)
void gemm_tc_kernel(const __half* __restrict__ Xh,
                    const __half* __restrict__ Wq_h, const __half* __restrict__ Wk_h,
                    const __half* __restrict__ Wv_h,
                    const float* __restrict__ bq, const float* __restrict__ bk,
                    const float* __restrict__ bv,
                    __half* __restrict__ qo, __half* __restrict__ ko,
                    __half* __restrict__ vo)
{
    const int z = blockIdx.z;
    const __half* Wh = (z == 0) ? Wq_h : (z == 1) ? Wk_h : Wv_h;
    const float* bias = (z == 0) ? bq : (z == 1) ? bk : bv;
    __half* gout = (z == 0) ? qo : (z == 1) ? ko : vo;
    const float scale = (z == 0) ? 0.18033688011112042f : 1.0f;

    extern __shared__ char smem[];
    const u32 sb = smem_u32(smem);
    const int tid = threadIdx.x;
    const int w = tid >> 5, lane = tid & 31;
    const int wm = w >> 1, wn = w & 1;
    const int bn = blockIdx.x * 128;
    const int bm = blockIdx.y * 128;

    float acc[2][8][4];
    #pragma unroll
    for (int mi = 0; mi < 2; mi++)
        #pragma unroll
        for (int j = 0; j < 8; j++)
            #pragma unroll
            for (int i = 0; i < 4; i++) acc[mi][j][i] = 0.0f;

    const int frow = (lane & 7) + ((lane >> 3) & 1) * 8;
    const u32 aoff = (u32)(frow * XRS + (lane >> 4) * 16);
    const u32 boff = (u32)(frow * WRS + (lane >> 4) * 16);

    const int xr = tid >> 3, xo = tid & 7;
    const int wr = tid >> 4, wo = tid & 15;

    #pragma unroll
    for (int pc = 0; pc < 2; pc++) {
        const u32 buf = sb + pc * GBUF;
        const int kb = pc * 64;
        #pragma unroll
        for (int i = 0; i < 4; i++) {
            int r = xr + i * 32;
            cp16(buf + (u32)(r * XRS + xo * 16), Xh + (size_t)(bm + r) * HH + kb + xo * 8);
        }
        #pragma unroll
        for (int i = 0; i < 4; i++) {
            int r = wr + i * 16;
            cp16(buf + GXT + (u32)(r * WRS + wo * 16), Wh + (size_t)(kb + r) * HH + bn + wo * 8);
        }
        CP_COMMIT();
    }

    for (int kc = 0; kc < 12; kc++) {
        if (kc < 11) { CP_WAIT1(); } else { CP_WAIT0(); }
        __syncthreads();

        if (kc < 10) {
            const u32 buf = sb + ((kc + 2) % 3) * GBUF;
            const int kb = (kc + 2) * 64;
            #pragma unroll
            for (int i = 0; i < 4; i++) {
                int r = xr + i * 32;
                cp16(buf + (u32)(r * XRS + xo * 16), Xh + (size_t)(bm + r) * HH + kb + xo * 8);
            }
            #pragma unroll
            for (int i = 0; i < 4; i++) {
                int r = wr + i * 16;
                cp16(buf + GXT + (u32)(r * WRS + wo * 16), Wh + (size_t)(kb + r) * HH + bn + wo * 8);
            }
            CP_COMMIT();
        }

        const u32 XT = sb + (kc % 3) * GBUF;
        const u32 WT = XT + GXT;

        #pragma unroll
        for (int kk = 0; kk < 4; kk++) {
            u32 ah[2][4];
            #pragma unroll
            for (int mi = 0; mi < 2; mi++) {
                u32 a = (u32)((wm * 32 + mi * 16) * XRS) + aoff + kk * 32;
                LDSM4(ah[mi], XT + a);
            }
            #pragma unroll
            for (int nt = 0; nt < 4; nt++) {
                u32 bo = (u32)(kk * 16 * WRS) + boff + (u32)(wn * 128 + nt * 32);
                u32 bh[4];
                LDSM4T(bh, WT + bo);
                #pragma unroll
                for (int mi = 0; mi < 2; mi++) {
                    MMA(acc[mi][2 * nt],     ah[mi], bh[0], bh[1]);
                    MMA(acc[mi][2 * nt + 1], ah[mi], bh[2], bh[3]);
                }
            }
        }
    }

    const int h  = (bn >> 6) + wn;
    const int cl = (lane & 3) * 2;
    const int rl = lane >> 2;
    #pragma unroll
    for (int j = 0; j < 8; j++) {
        const int d = j * 8 + cl;
        const float bx = bias[bn + wn * 64 + d];
        const float by = bias[bn + wn * 64 + d + 1];
        #pragma unroll
        for (int mi = 0; mi < 2; mi++) {
            #pragma unroll
            for (int rr = 0; rr < 2; rr++) {
                const int m = bm + wm * 32 + mi * 16 + rl + rr * 8;
                const int b = m >> 12, s = m & 4095;
                const size_t o = ((size_t)(b * NHH + h) * SS + s) * DHH + d;
                const float y0 = (acc[mi][j][2 * rr]     + bx) * scale;
                const float y1 = (acc[mi][j][2 * rr + 1] + by) * scale;
                *(u32*)&gout[o] = cvtpack(y0, y1);
            }
        }
    }
}

// ---------------------------------------------------------------------------
// mma.sync flash attention v7: v5 pipeline, KV-split 2x, fp16 partial ctx.
// ---------------------------------------------------------------------------
#define RS 144
#define ARR_BYTES (128 * RS)
#define BUF_BYTES (2 * ARR_BYTES)
#define SM_TOTAL  (2 * BUF_BYTES)
#define NT_HALF (32 / KVSPLIT)

__global__ __launch_bounds__(128, 2)
void attn_mma_kernel(const __half* __restrict__ qh_g,
                     const __half* __restrict__ kh_g,
                     const __half* __restrict__ vh_g,
                     __half* __restrict__ pctx0, __half* __restrict__ pctx1,
                     float* __restrict__ pl0, float* __restrict__ pl1)
{
    extern __shared__ char smem[];
    const u32 sb = smem_u32(smem);
    const int tid  = threadIdx.x;
    const int w    = tid >> 5;
    const int lane = tid & 31;
    const int qt = blockIdx.x;
    const int bh = blockIdx.y;
    const int kz = blockIdx.z;
    const int b = bh / NHH, h = bh % NHH;
    __half* __restrict__ pctx = kz ? pctx1 : pctx0;
    float* __restrict__ pl    = kz ? pl1 : pl0;

    const size_t bh_base = (size_t)bh * SS * DHH;
    const int t0 = kz * NT_HALF;

    {
        const u32 QB = sb + BUF_BYTES;
        const __half* qg = qh_g + bh_base + (size_t)qt * 128 * DHH;
        #pragma unroll
        for (int i = 0; i < 8; i++) {
            int c = tid + i * 128;
            int r = c >> 3, o = c & 7;
            cp16(QB + (u32)(r * RS + o * 16), qg + (size_t)r * DHH + o * 8);
        }
        CP_COMMIT();
        CP_WAIT0();
        __syncthreads();
    }

    const int frow = (lane & 7) + ((lane >> 3) & 1) * 8;
    u32 qf[2][4][4];
    {
        const u32 QB = sb + BUF_BYTES;
        #pragma unroll
        for (int mi = 0; mi < 2; mi++) {
            u32 rbase = (u32)((w * 32 + mi * 16 + frow) * RS + (lane >> 4) * 16);
            #pragma unroll
            for (int k = 0; k < 4; k++)
                LDSM4(qf[mi][k], QB + rbase + k * 32);
        }
    }
    __syncthreads();

    float ctx[2][8][4];
    #pragma unroll
    for (int mi = 0; mi < 2; mi++)
        #pragma unroll
        for (int n = 0; n < 8; n++)
            #pragma unroll
            for (int i = 0; i < 4; i++) ctx[mi][n][i] = 0.0f;
    float ls[2][2] = {{0.f, 0.f}, {0.f, 0.f}};

    const u32 koff = (u32)(((lane >> 4) * 8 + (lane & 7)) * RS + ((lane >> 3) & 1) * 16);
    const u32 voff = (u32)((((lane >> 3) & 1) * 8 + (lane & 7)) * RS + (lane >> 4) * 16);

    {
        const size_t gb = bh_base + (size_t)t0 * 128 * DHH;
        #pragma unroll
        for (int i = 0; i < 8; i++) {
            int c = tid + i * 128;
            int r = c >> 3, o = c & 7;
            u32 so = (u32)(r * RS + o * 16);
            cp16(sb + so,             kh_g + gb + (size_t)r * DHH + o * 8);
            cp16(sb + ARR_BYTES + so, vh_g + gb + (size_t)r * DHH + o * 8);
        }
        CP_COMMIT();
    }

    for (int t = 0; t < NT_HALF; ++t) {
        if (t < NT_HALF - 1) {
            const u32 nb = sb + ((t + 1) & 1) * BUF_BYTES;
            const size_t gb = bh_base + (size_t)(t0 + t + 1) * 128 * DHH;
            #pragma unroll
            for (int i = 0; i < 8; i++) {
                int c = tid + i * 128;
                int r = c >> 3, o = c & 7;
                u32 so = (u32)(r * RS + o * 16);
                cp16(nb + so,             kh_g + gb + (size_t)r * DHH + o * 8);
                cp16(nb + ARR_BYTES + so, vh_g + gb + (size_t)r * DHH + o * 8);
            }
            CP_COMMIT();
            CP_WAIT1();
        } else {
            CP_WAIT0();
        }
        __syncthreads();

        const u32 KH = sb + (t & 1) * BUF_BYTES;
        const u32 VS = KH + ARR_BYTES;

        u32 hls[2][2] = {{0u, 0u}, {0u, 0u}};

        u32 khf[4][4];
        #pragma unroll
        for (int k = 0; k < 4; k++)
            LDSM4(khf[k], KH + koff + k * 32);

        u32 scur[4] = {0u, 0u, 0u, 0u};
        #pragma unroll
        for (int k = 0; k < 4; k++) {
            MMAH(&scur[0], qf[0][k], khf[k][0], khf[k][1]);
            MMAH(&scur[2], qf[0][k], khf[k][2], khf[k][3]);
        }

        u32 vf[4][4];

        #pragma unroll
        for (int st = 0; st < 16; st++) {
            const int j  = st >> 1;
            const int mi = st & 1;

            if (mi == 0) {
                const u32 bj = (u32)(j * 16 * RS);
                #pragma unroll
                for (int tt = 0; tt < 4; tt++)
                    LDSM4T(vf[tt], VS + bj + voff + tt * 32);
            }

            u32 pa[4];
            pa[0] = ex2h2(scur[0]);
            pa[1] = ex2h2(scur[1]);
            pa[2] = ex2h2(scur[2]);
            pa[3] = ex2h2(scur[3]);

            u32 snext[4] = {0u, 0u, 0u, 0u};
            if (st < 15) {
                const int mi2 = (st + 1) & 1;
                if (mi2 == 0) {
                    const int j2 = (st + 1) >> 1;
                    const u32 bj2 = (u32)(j2 * 16 * RS);
                    #pragma unroll
                    for (int k = 0; k < 4; k++)
                        LDSM4(khf[k], KH + bj2 + koff + k * 32);
                }
                #pragma unroll
                for (int k = 0; k < 4; k++) {
                    MMAH(&snext[0], qf[mi2][k], khf[k][0], khf[k][1]);
                    MMAH(&snext[2], qf[mi2][k], khf[k][2], khf[k][3]);
                }
            }

            hls[mi][0] = haddp(hls[mi][0], haddp(pa[0], pa[2]));
            hls[mi][1] = haddp(hls[mi][1], haddp(pa[1], pa[3]));

            #pragma unroll
            for (int tt = 0; tt < 4; tt++) {
                MMA(ctx[mi][2 * tt],     pa, vf[tt][0], vf[tt][1]);
                MMA(ctx[mi][2 * tt + 1], pa, vf[tt][2], vf[tt][3]);
            }

            #pragma unroll
            for (int i = 0; i < 4; i++) scur[i] = snext[i];
        }

        #pragma unroll
        for (int mi = 0; mi < 2; mi++) {
            float2 f0 = __half22float2(*(__half2*)&hls[mi][0]);
            float2 f1 = __half22float2(*(__half2*)&hls[mi][1]);
            ls[mi][0] += f0.x + f0.y;
            ls[mi][1] += f1.x + f1.y;
        }
        __syncthreads();
    }

    // ---- write fp16 partial ctx + fp32 partial row sums ----
    #pragma unroll
    for (int mi = 0; mi < 2; mi++) {
        float l0 = ls[mi][0], l1 = ls[mi][1];
        l0 += __shfl_xor_sync(0xffffffffu, l0, 1);
        l0 += __shfl_xor_sync(0xffffffffu, l0, 2);
        l1 += __shfl_xor_sync(0xffffffffu, l1, 1);
        l1 += __shfl_xor_sync(0xffffffffu, l1, 2);

        const int rloc = qt * 128 + w * 32 + mi * 16 + (lane >> 2);
        if ((lane & 3) == 0) {
            pl[(size_t)bh * SS + rloc]     = l0;
            pl[(size_t)bh * SS + rloc + 8] = l1;
        }

        const int colb = 2 * (lane & 3);
        __half* o0 = pctx + ((size_t)(b * SS) + rloc) * HH + h * DHH + colb;
        __half* o1 = o0 + 8 * HH;
        #pragma unroll
        for (int n = 0; n < 8; n++) {
            *(u32*)(o0 + 8 * n) = cvtpack(ctx[mi][n][0], ctx[mi][n][1]);
            *(u32*)(o1 + 8 * n) = cvtpack(ctx[mi][n][2], ctx[mi][n][3]);
        }
    }
}

// ---------------------------------------------------------------------------
// Combine: out = tanh((c0+c1)/(l0+l1)), fp16 partial reads
// ---------------------------------------------------------------------------
__global__ __launch_bounds__(256)
void combine_kernel(const __half* __restrict__ pctx0, const __half* __restrict__ pctx1,
                    const float* __restrict__ pl0, const float* __restrict__ pl1,
                    float* __restrict__ out)
{
    const size_t i4 = (size_t)blockIdx.x * 256 + threadIdx.x;
    const size_t o = i4 * 4;
    const int row = (int)(o / HH);
    const int col = (int)(o % HH);
    const int h = col >> 6;
    const int b = row >> 12, s = row & 4095;
    const size_t li = (size_t)(b * NHH + h) * SS + s;

    const float inv = 1.0f / (pl0[li] + pl1[li]);
    uint2 h0 = *(const uint2*)&pctx0[o];
    uint2 h1 = *(const uint2*)&pctx1[o];
    float2 a0 = __half22float2(*(__half2*)&h0.x);
    float2 a1 = __half22float2(*(__half2*)&h0.y);
    float2 b0 = __half22float2(*(__half2*)&h1.x);
    float2 b1 = __half22float2(*(__half2*)&h1.y);
    float4 r;
    r.x = tanhf((a0.x + b0.x) * inv);
    r.y = tanhf((a0.y + b0.y) * inv);
    r.z = tanhf((a1.x + b1.x) * inv);
    r.w = tanhf((a1.y + b1.y) * inv);
    *(float4*)&out[o] = r;
}

// ---------------------------------------------------------------------------
extern "C" void kernel_launch(void* const* d_in, const int* in_sizes, int n_in,
                              void* d_out, int out_size)
{
    const float* x  = (const float*)d_in[0];
    const float* Wq = (const float*)d_in[1];
    const float* bq = (const float*)d_in[2];
    const float* Wk = (const float*)d_in[3];
    const float* bk = (const float*)d_in[4];
    const float* Wv = (const float*)d_in[5];
    const float* bv = (const float*)d_in[6];
    float* out = (float*)d_out;

    __half *xh, *wq, *wk, *wv, *qh, *kh, *vh, *pc;
    float *plv;
    cudaGetSymbolAddress((void**)&xh, g_xh);
    cudaGetSymbolAddress((void**)&wq, g_wq);
    cudaGetSymbolAddress((void**)&wk, g_wk);
    cudaGetSymbolAddress((void**)&wv, g_wv);
    cudaGetSymbolAddress((void**)&qh, g_qh);
    cudaGetSymbolAddress((void**)&kh, g_kh);
    cudaGetSymbolAddress((void**)&vh, g_vh);
    cudaGetSymbolAddress((void**)&pc, g_pctx);
    cudaGetSymbolAddress((void**)&plv, g_pl);
    __half* pc0 = pc;
    __half* pc1 = pc + (size_t)MM * HH;
    float* pl0 = plv;
    float* pl1 = plv + (size_t)NBH * SS;

    cudaFuncSetAttribute(gemm_tc_kernel, cudaFuncAttributeMaxDynamicSharedMemorySize, GSM);
    cudaFuncSetAttribute(attn_mma_kernel, cudaFuncAttributeMaxDynamicSharedMemorySize, SM_TOTAL);

    conv_all_kernel<<<MM + 3 * HH, 192>>>(x, Wq, Wk, Wv, xh, wq, wk, wv);

    dim3 ggrid(HH / 128, MM / 128, 3);
    gemm_tc_kernel<<<ggrid, 256, GSM>>>(xh, wq, wk, wv, bq, bk, bv, qh, kh, vh);

    dim3 agrid(SS / 128, NBH, KVSPLIT);
    attn_mma_kernel<<<agrid, 128, SM_TOTAL>>>(qh, kh, vh, pc0, pc1, pl0, pl1);

    combine_kernel<<<(MM * HH) / (4 * 256), 256>>>(pc0, pc1, pl0, pl1, out);
}